// round 6
// baseline (speedup 1.0000x reference)
#include <cuda_runtime.h>
#include <math.h>

// Problem constants
#define BB    32
#define LL    65536          // T*K
#define CC    6
#define POSB  1024           // positions per block
#define NCH   (LL / POSB)    // 64 chunks per batch
#define TPB   512            // 16 warps; thread owns 2 positions x 6 channels
#define GRID  (BB * NCH)     // 2048 blocks

// -ln(a), a = 1 - theta*dt = 0.99999 ; a^{-t} = exp(t*LPc)
#define LPc 1.0000050000333335e-05f
// sqrt(2*theta*dt) = sqrt(2e-5)
#define SQc 4.4721359549995794e-03f
#define TWO_PI 6.2831853071795864f
#define INV_LM1 (1.0f / 65535.0f)

__device__ float g_W[BB * NCH * CC];  // chunk weighted partial sums

__device__ __forceinline__ float ch_std0(int c)  { return (c < 3) ? 0.2f   : 0.015f; }
__device__ __forceinline__ float ch_noise(int c) { return (c < 3) ? 0.1f   : 0.01f;  }
__device__ __forceinline__ float ch_tcoef(int c) { return (c < 3) ? 0.001f : 0.01f;  }

// ---------------------------------------------------------------------------
// 12 walk floats feeding 2 positions (shifted: w_t uses walk[t-1]; w_0 = 0).
// ---------------------------------------------------------------------------
__device__ __forceinline__ void load_walk12(const float* __restrict__ walk,
                                            int b, int p0, float wv[12]) {
    if (p0 == 0) {
        const float* w2 = walk + (size_t)b * (LL - 1) * CC;
        #pragma unroll
        for (int i = 0; i < 6; ++i) wv[i] = 0.0f;
        #pragma unroll
        for (int i = 0; i < 3; ++i) {
            float2 v = *(const float2*)(w2 + 2 * i);
            wv[6 + 2 * i] = v.x; wv[7 + 2 * i] = v.y;
        }
    } else {
        const float* wp = walk + (size_t)b * (LL - 1) * CC + (size_t)(p0 - 1) * CC;
        #pragma unroll
        for (int i = 0; i < 6; ++i) {
            float2 v = *(const float2*)(wp + 2 * i);
            wv[2 * i] = v.x; wv[2 * i + 1] = v.y;
        }
    }
}

// ---------------------------------------------------------------------------
// Phase A: W[b,k,c] = sum over chunk of walk[t-1]*ds_c*a^{-t}
// ---------------------------------------------------------------------------
__global__ __launch_bounds__(TPB, 2) void chunk_sum_kernel(const float* __restrict__ walk) {
    __shared__ float wsum[16][CC];
    const int bx = blockIdx.x;
    const int b = bx >> 6, k = bx & (NCH - 1);
    const int tid = threadIdx.x;
    const int w = tid >> 5, l = tid & 31;
    const int p0 = k * POSB + tid * 2;

    float wv[12];
    load_walk12(walk, b, p0, wv);

    const float ainv0 = expf((float)p0 * LPc);
    const float ainv1 = ainv0 * (1.0f + LPc);   // a^{-1} ~ e^{LPc}, err 5e-11

    float t6[CC];
    #pragma unroll
    for (int c = 0; c < CC; ++c) {
        float ds = ch_std0(c) * SQc;
        t6[c] = wv[c] * ds * ainv0 + wv[6 + c] * ds * ainv1;
    }
    #pragma unroll
    for (int d = 16; d >= 1; d >>= 1)
        #pragma unroll
        for (int c = 0; c < CC; ++c)
            t6[c] += __shfl_down_sync(0xffffffffu, t6[c], d);
    if (l == 0)
        #pragma unroll
        for (int c = 0; c < CC; ++c) wsum[w][c] = t6[c];
    __syncthreads();
    if (w == 0 && l < 16) {
        float v[CC];
        #pragma unroll
        for (int c = 0; c < CC; ++c) v[c] = wsum[l][c];
        #pragma unroll
        for (int d = 8; d >= 1; d >>= 1)
            #pragma unroll
            for (int c = 0; c < CC; ++c)
                v[c] += __shfl_down_sync(0x0000ffffu, v[c], d);
        if (l == 0)
            #pragma unroll
            for (int c = 0; c < CC; ++c) g_W[(b * NCH + k) * CC + c] = v[c];
    }
}

// ---------------------------------------------------------------------------
// Phase B (fused): register scan + inline carry (sum of predecessor chunk
// aggregates, deterministic, no spin) + epilogue. 2 barriers total.
// ---------------------------------------------------------------------------
__global__ __launch_bounds__(TPB, 2) void apply_kernel(
    const float* __restrict__ imu,
    const float* __restrict__ eps0,
    const float* __restrict__ walk,
    const float* __restrict__ meas,
    float* __restrict__ out)
{
    __shared__ float wsum[16][CC];
    __shared__ float wexc[16][CC];
    __shared__ float bcast[CC];

    const int bx = blockIdx.x;
    const int b = bx >> 6, k = bx & (NCH - 1);
    const int tid = threadIdx.x;
    const int w = tid >> 5, l = tid & 31;
    const int tstart = k * POSB;
    const int p0 = tstart + tid * 2;

    float wv[12];
    load_walk12(walk, b, p0, wv);

    const float ainv0 = expf((float)p0 * LPc);
    const float ainv1 = ainv0 * (1.0f + LPc);
    const float apos0 = expf(-(float)p0 * LPc);
    const float apos1 = apos0 * (1.0f - LPc);

    float w0[CC], w1[CC], t6[CC];
    #pragma unroll
    for (int c = 0; c < CC; ++c) {
        float ds = ch_std0(c) * SQc;
        w0[c] = wv[c] * ds * ainv0;
        w1[c] = wv[6 + c] * ds * ainv1;
        t6[c] = w0[c] + w1[c];
    }

    // warp-inclusive scan per channel (6 parallel chains)
    float incl[CC];
    #pragma unroll
    for (int c = 0; c < CC; ++c) incl[c] = t6[c];
    #pragma unroll
    for (int d = 1; d < 32; d <<= 1)
        #pragma unroll
        for (int c = 0; c < CC; ++c) {
            float o = __shfl_up_sync(0xffffffffu, incl[c], d);
            if (l >= d) incl[c] += o;
        }
    if (l == 31)
        #pragma unroll
        for (int c = 0; c < CC; ++c) wsum[w][c] = incl[c];
    __syncthreads();

    // warp 0: second-level scan over 16 warp totals + inline carry over chunks
    if (w == 0) {
        // carry: sum g_W[b, 0..k-1, c]; each lane covers chunks l and 32+l.
        float pv[CC];
        {
            const float* gwb = &g_W[b * NCH * CC];
            #pragma unroll
            for (int c = 0; c < CC; ++c) pv[c] = 0.0f;
            if (l < k) {
                const float* gw = gwb + l * CC;
                #pragma unroll
                for (int c = 0; c < CC; ++c) pv[c] = gw[c];
            }
            if (32 + l < k) {
                const float* gw = gwb + (32 + l) * CC;
                #pragma unroll
                for (int c = 0; c < CC; ++c) pv[c] += gw[c];
            }
        }

        float v[CC], inc2[CC];
        #pragma unroll
        for (int c = 0; c < CC; ++c) {
            v[c] = (l < 16) ? wsum[l][c] : 0.0f;
            inc2[c] = v[c];
        }
        #pragma unroll
        for (int d = 1; d < 16; d <<= 1)
            #pragma unroll
            for (int c = 0; c < CC; ++c) {
                float o = __shfl_up_sync(0xffffffffu, inc2[c], d);
                if (l >= d) inc2[c] += o;
            }
        if (l < 16)
            #pragma unroll
            for (int c = 0; c < CC; ++c) wexc[l][c] = inc2[c] - v[c];

        // reduce carry across lanes (fixed tree order -> deterministic)
        #pragma unroll
        for (int d = 16; d >= 1; d >>= 1)
            #pragma unroll
            for (int c = 0; c < CC; ++c)
                pv[c] += __shfl_down_sync(0xffffffffu, pv[c], d);
        if (l == 0)
            #pragma unroll
            for (int c = 0; c < CC; ++c) bcast[c] = pv[c];
    }
    __syncthreads();

    // bias for both positions, in registers
    float bias0[CC], bias1[CC];
    #pragma unroll
    for (int c = 0; c < CC; ++c) {
        float carry = eps0[b * CC + c] * ch_std0(c) + bcast[c];
        float base = carry + wexc[w][c] + (incl[c] - t6[c]);
        bias0[c] = (base + w0[c]) * apos0;
        bias1[c] = (base + t6[c]) * apos1;
    }

    // temperature inline (no table): temp(t) = 20 + 5*sin(2*pi*tt) + 2*tt
    const float tt0 = (float)p0 * INV_LM1;
    const float tt1 = (float)(p0 + 1) * INV_LM1;
    const float tm0 = 20.0f + 5.0f * __sinf(TWO_PI * tt0) + 2.0f * tt0;
    const float tm1 = 20.0f + 5.0f * __sinf(TWO_PI * tt1) + 2.0f * tt1;

    // fused epilogue: 12 contiguous floats, 3x float4 in/out
    const size_t gb = ((size_t)b * LL + tstart) * CC + (size_t)tid * 12;

    float bias[12], tadd[12], ns[12];
    #pragma unroll
    for (int c = 0; c < CC; ++c) {
        bias[c] = bias0[c];           bias[6 + c] = bias1[c];
        tadd[c] = tm0 * ch_tcoef(c);  tadd[6 + c] = tm1 * ch_tcoef(c);
        ns[c] = ch_noise(c);          ns[6 + c] = ch_noise(c);
    }
    #pragma unroll
    for (int q = 0; q < 3; ++q) {
        float4 vi = *(const float4*)(imu + gb + q * 4);
        float4 vm = *(const float4*)(meas + gb + q * 4);
        float4 o4;
        o4.x = vi.x + bias[q * 4 + 0] + vm.x * ns[q * 4 + 0] + tadd[q * 4 + 0];
        o4.y = vi.y + bias[q * 4 + 1] + vm.y * ns[q * 4 + 1] + tadd[q * 4 + 1];
        o4.z = vi.z + bias[q * 4 + 2] + vm.z * ns[q * 4 + 2] + tadd[q * 4 + 2];
        o4.w = vi.w + bias[q * 4 + 3] + vm.w * ns[q * 4 + 3] + tadd[q * 4 + 3];
        *(float4*)(out + gb + q * 4) = o4;
    }
}

// ---------------------------------------------------------------------------
extern "C" void kernel_launch(void* const* d_in, const int* in_sizes, int n_in,
                              void* d_out, int out_size) {
    const float* imu  = (const float*)d_in[0];   // [32, 4096, 16, 6]
    const float* eps0 = (const float*)d_in[1];   // [32, 6]
    const float* walk = (const float*)d_in[2];   // [32, 65535, 6]
    const float* meas = (const float*)d_in[3];   // [32, 65536, 6]
    float* out = (float*)d_out;

    chunk_sum_kernel<<<GRID, TPB>>>(walk);
    apply_kernel<<<GRID, TPB>>>(imu, eps0, walk, meas, out);
}

// round 8
// speedup vs baseline: 1.4567x; 1.4567x over previous
#include <cuda_runtime.h>
#include <math.h>

// Problem constants
#define BB    32
#define LL    65536           // T*K
#define CC    6
#define POSB  1024            // chunk size (granularity of g_W/g_E)
#define NCH   (LL / POSB)     // 64 chunks per batch
#define TPB   512
#define GRID_A (BB * NCH)     // 2048 blocks for apply (2 positions/thread)
#define GRID_P (BB * NCH / 2) // 1024 blocks for prep  (4 positions/thread)

// -ln(a), a = 1 - theta*dt = 0.99999 ; a^{-t} = exp(t*LPc)
#define LPc 1.0000050000333335e-05f
// sqrt(2*theta*dt) = sqrt(2e-5)
#define SQc 4.4721359549995794e-03f
#define TWO_PI 6.2831853071795864f
#define INV_LM1 (1.0f / 65535.0f)

// Layout [b][c][k] so the carry kernel reads/writes coalesced.
__device__ float g_W[BB * CC * NCH];   // chunk weighted partial sums
__device__ float g_E[BB * CC * NCH];   // exclusive prefix over chunks
__device__ float g_temp[LL];           // temperature curve

__device__ __forceinline__ float ch_std0(int c)  { return (c < 3) ? 0.2f   : 0.015f; }
__device__ __forceinline__ float ch_noise(int c) { return (c < 3) ? 0.1f   : 0.01f;  }
__device__ __forceinline__ float ch_tcoef(int c) { return (c < 3) ? 0.001f : 0.01f;  }

// ---------------------------------------------------------------------------
// 12 walk floats feeding 2 positions (shifted: w_t uses walk[t-1]; w_0 = 0).
// ---------------------------------------------------------------------------
__device__ __forceinline__ void load_walk12(const float* __restrict__ walk,
                                            int b, int p0, float wv[12]) {
    if (p0 == 0) {
        const float* w2 = walk + (size_t)b * (LL - 1) * CC;
        #pragma unroll
        for (int i = 0; i < 6; ++i) wv[i] = 0.0f;
        #pragma unroll
        for (int i = 0; i < 3; ++i) {
            float2 v = *(const float2*)(w2 + 2 * i);
            wv[6 + 2 * i] = v.x; wv[7 + 2 * i] = v.y;
        }
    } else {
        const float* wp = walk + (size_t)b * (LL - 1) * CC + (size_t)(p0 - 1) * CC;
        #pragma unroll
        for (int i = 0; i < 6; ++i) {
            float2 v = *(const float2*)(wp + 2 * i);
            wv[2 * i] = v.x; wv[2 * i + 1] = v.y;
        }
    }
}

// ---------------------------------------------------------------------------
// Prep: chunk aggregates (2 chunks per block, 4 positions/thread) + temp
// table written by the b==0 blocks. No cross-block dependencies.
// ---------------------------------------------------------------------------
__global__ __launch_bounds__(TPB, 2) void prep_kernel(const float* __restrict__ walk) {
    __shared__ float wsum[16][CC];

    const int bx = blockIdx.x;
    const int b = bx >> 5, kk = bx & 31;       // kk: 2048-position super-chunk
    const int tid = threadIdx.x;
    const int w = tid >> 5, l = tid & 31;
    const int p0 = kk * (2 * POSB) + tid * 4;  // 4 consecutive positions

    float wa[12], wb[12];
    load_walk12(walk, b, p0, wa);
    load_walk12(walk, b, p0 + 2, wb);

    const float ai0 = expf((float)p0 * LPc);
    const float ai1 = ai0 * (1.0f + LPc);
    const float ai2 = ai1 * (1.0f + LPc);
    const float ai3 = ai2 * (1.0f + LPc);

    float t6[CC];
    #pragma unroll
    for (int c = 0; c < CC; ++c) {
        float ds = ch_std0(c) * SQc;
        t6[c] = ds * (wa[c] * ai0 + wa[6 + c] * ai1 + wb[c] * ai2 + wb[6 + c] * ai3);
    }
    #pragma unroll
    for (int d = 16; d >= 1; d >>= 1)
        #pragma unroll
        for (int c = 0; c < CC; ++c)
            t6[c] += __shfl_down_sync(0xffffffffu, t6[c], d);
    if (l == 0)
        #pragma unroll
        for (int c = 0; c < CC; ++c) wsum[w][c] = t6[c];

    // temp table: the 32 b==0 blocks cover all 65536 positions (4 per thread)
    if (b == 0) {
        #pragma unroll
        for (int i = 0; i < 4; ++i) {
            int t = p0 + i;
            float tt = (float)t * INV_LM1;
            g_temp[t] = 20.0f + 5.0f * __sinf(TWO_PI * tt) + 2.0f * tt;
        }
    }
    __syncthreads();

    // warp 0: lanes 0-7 reduce warps 0-7 (chunk 2kk), lanes 8-15 warps 8-15
    if (w == 0 && l < 16) {
        float v[CC];
        #pragma unroll
        for (int c = 0; c < CC; ++c) v[c] = wsum[l][c];
        #pragma unroll
        for (int d = 4; d >= 1; d >>= 1)
            #pragma unroll
            for (int c = 0; c < CC; ++c)
                v[c] += __shfl_down_sync(0x0000ffffu, v[c], d, 8);
        if ((l & 7) == 0) {
            int k = 2 * kk + (l >> 3);
            #pragma unroll
            for (int c = 0; c < CC; ++c)
                g_W[(b * CC + c) * NCH + k] = v[c];   // [b][c][k] layout
        }
    }
}

// ---------------------------------------------------------------------------
// Carry: exclusive prefix over 64 chunks, one warp per (b,c) pair.
// Coalesced float2 reads/writes; shuffle scan. 192 warps = 6 blocks x 32.
// ---------------------------------------------------------------------------
__global__ __launch_bounds__(1024) void carry_kernel() {
    const int w = threadIdx.x >> 5, l = threadIdx.x & 31;
    const int pair = blockIdx.x * 32 + w;       // 0..191 == (b*CC+c)
    const float* src = &g_W[pair * NCH];
    float* dst = &g_E[pair * NCH];

    float2 v = *(const float2*)(src + 2 * l);   // chunks 2l, 2l+1
    float s = v.x + v.y;
    float inc = s;
    #pragma unroll
    for (int d = 1; d < 32; d <<= 1) {
        float o = __shfl_up_sync(0xffffffffu, inc, d);
        if (l >= d) inc += o;
    }
    float excl = inc - s;
    float2 e; e.x = excl; e.y = excl + v.x;
    *(float2*)(dst + 2 * l) = e;
}

// ---------------------------------------------------------------------------
// Apply (round-4 proven version): register scan + g_E/g_temp tables.
// ---------------------------------------------------------------------------
__global__ __launch_bounds__(TPB, 2) void apply_kernel(
    const float* __restrict__ imu,
    const float* __restrict__ eps0,
    const float* __restrict__ walk,
    const float* __restrict__ meas,
    float* __restrict__ out)
{
    __shared__ float wsum[16][CC];
    __shared__ float wexc[16][CC];

    const int bx = blockIdx.x;
    const int b = bx >> 6, k = bx & (NCH - 1);
    const int tid = threadIdx.x;
    const int w = tid >> 5, l = tid & 31;
    const int tstart = k * POSB;
    const int p0 = tstart + tid * 2;

    float wv[12];
    load_walk12(walk, b, p0, wv);

    const float ainv0 = expf((float)p0 * LPc);
    const float ainv1 = ainv0 * (1.0f + LPc);
    const float apos0 = expf(-(float)p0 * LPc);
    const float apos1 = apos0 * (1.0f - LPc);

    float w0[CC], w1[CC], t6[CC];
    #pragma unroll
    for (int c = 0; c < CC; ++c) {
        float ds = ch_std0(c) * SQc;
        w0[c] = wv[c] * ds * ainv0;
        w1[c] = wv[6 + c] * ds * ainv1;
        t6[c] = w0[c] + w1[c];
    }

    float incl[CC];
    #pragma unroll
    for (int c = 0; c < CC; ++c) incl[c] = t6[c];
    #pragma unroll
    for (int d = 1; d < 32; d <<= 1)
        #pragma unroll
        for (int c = 0; c < CC; ++c) {
            float o = __shfl_up_sync(0xffffffffu, incl[c], d);
            if (l >= d) incl[c] += o;
        }
    if (l == 31)
        #pragma unroll
        for (int c = 0; c < CC; ++c) wsum[w][c] = incl[c];
    __syncthreads();

    if (w == 0 && l < 16) {
        float v[CC], inc2[CC];
        #pragma unroll
        for (int c = 0; c < CC; ++c) { v[c] = wsum[l][c]; inc2[c] = v[c]; }
        #pragma unroll
        for (int d = 1; d < 16; d <<= 1)
            #pragma unroll
            for (int c = 0; c < CC; ++c) {
                float o = __shfl_up_sync(0x0000ffffu, inc2[c], d);
                if (l >= d) inc2[c] += o;
            }
        #pragma unroll
        for (int c = 0; c < CC; ++c) wexc[l][c] = inc2[c] - v[c];
    }
    __syncthreads();

    float bias0[CC], bias1[CC];
    #pragma unroll
    for (int c = 0; c < CC; ++c) {
        float carry = eps0[b * CC + c] * ch_std0(c) + g_E[(b * CC + c) * NCH + k];
        float base = carry + wexc[w][c] + (incl[c] - t6[c]);
        bias0[c] = (base + w0[c]) * apos0;
        bias1[c] = (base + t6[c]) * apos1;
    }

    const size_t gb = ((size_t)b * LL + tstart) * CC + (size_t)tid * 12;
    const float tm0 = g_temp[p0], tm1 = g_temp[p0 + 1];

    float bias[12], tadd[12], ns[12];
    #pragma unroll
    for (int c = 0; c < CC; ++c) {
        bias[c] = bias0[c];           bias[6 + c] = bias1[c];
        tadd[c] = tm0 * ch_tcoef(c);  tadd[6 + c] = tm1 * ch_tcoef(c);
        ns[c] = ch_noise(c);          ns[6 + c] = ch_noise(c);
    }
    #pragma unroll
    for (int q = 0; q < 3; ++q) {
        float4 vi = *(const float4*)(imu + gb + q * 4);
        float4 vm = *(const float4*)(meas + gb + q * 4);
        float4 o4;
        o4.x = vi.x + bias[q * 4 + 0] + vm.x * ns[q * 4 + 0] + tadd[q * 4 + 0];
        o4.y = vi.y + bias[q * 4 + 1] + vm.y * ns[q * 4 + 1] + tadd[q * 4 + 1];
        o4.z = vi.z + bias[q * 4 + 2] + vm.z * ns[q * 4 + 2] + tadd[q * 4 + 2];
        o4.w = vi.w + bias[q * 4 + 3] + vm.w * ns[q * 4 + 3] + tadd[q * 4 + 3];
        *(float4*)(out + gb + q * 4) = o4;
    }
}

// ---------------------------------------------------------------------------
extern "C" void kernel_launch(void* const* d_in, const int* in_sizes, int n_in,
                              void* d_out, int out_size) {
    const float* imu  = (const float*)d_in[0];   // [32, 4096, 16, 6]
    const float* eps0 = (const float*)d_in[1];   // [32, 6]
    const float* walk = (const float*)d_in[2];   // [32, 65535, 6]
    const float* meas = (const float*)d_in[3];   // [32, 65536, 6]
    float* out = (float*)d_out;

    prep_kernel<<<GRID_P, TPB>>>(walk);
    carry_kernel<<<CC, 1024>>>();
    apply_kernel<<<GRID_A, TPB>>>(imu, eps0, walk, meas, out);
}

// round 9
// speedup vs baseline: 1.6297x; 1.1188x over previous
#include <cuda_runtime.h>
#include <math.h>

// Problem constants
#define BB    32
#define LL    65536           // T*K
#define CC    6
#define POSB  1024            // chunk size (granularity of g_W/g_E)
#define NCH   (LL / POSB)     // 64 chunks per batch
#define TPB   512
#define PTPB  384             // prep threads (multiple of 3!)
#define GRID_A (BB * NCH)     // 2048 blocks for apply
#define GRID_P (BB * NCH)     // 2048 blocks for prep (1 chunk each)

// -ln(a), a = 1 - theta*dt = 0.99999 ; a^{-t} = exp(t*LPc)
#define LPc 1.0000050000333335e-05f
// a^{-128} = exp(128*LPc)
#define STEP128 1.0012808260f
// sqrt(2*theta*dt) = sqrt(2e-5)
#define SQc 4.4721359549995794e-03f
#define TWO_PI 6.2831853071795864f
#define INV_LM1 (1.0f / 65535.0f)

// Layout [b][c][k] so carry reads/writes coalesced.
__device__ float g_W[BB * CC * NCH];   // walk-row-block weighted partial sums
__device__ float g_E[BB * CC * NCH];   // exclusive prefix over blocks
__device__ float g_temp[LL];           // temperature curve

__device__ __forceinline__ float ch_std0(int c)  { return (c < 3) ? 0.2f   : 0.015f; }
__device__ __forceinline__ float ch_noise(int c) { return (c < 3) ? 0.1f   : 0.01f;  }
__device__ __forceinline__ float ch_tcoef(int c) { return (c < 3) ? 0.001f : 0.01f;  }

// ---------------------------------------------------------------------------
// 12 walk floats feeding 2 positions (shifted: w_t uses walk[t-1]; w_0 = 0).
// ---------------------------------------------------------------------------
__device__ __forceinline__ void load_walk12(const float* __restrict__ walk,
                                            int b, int p0, float wv[12]) {
    if (p0 == 0) {
        const float* w2 = walk + (size_t)b * (LL - 1) * CC;
        #pragma unroll
        for (int i = 0; i < 6; ++i) wv[i] = 0.0f;
        #pragma unroll
        for (int i = 0; i < 3; ++i) {
            float2 v = *(const float2*)(w2 + 2 * i);
            wv[6 + 2 * i] = v.x; wv[7 + 2 * i] = v.y;
        }
    } else {
        const float* wp = walk + (size_t)b * (LL - 1) * CC + (size_t)(p0 - 1) * CC;
        #pragma unroll
        for (int i = 0; i < 6; ++i) {
            float2 v = *(const float2*)(wp + 2 * i);
            wv[2 * i] = v.x; wv[2 * i + 1] = v.y;
        }
    }
}

// ---------------------------------------------------------------------------
// Prep: fully-coalesced phase-decomposed chunk aggregates.
// Block = one walk-row block [kb*1024, (kb+1)*1024). Thread's float2 index
// mod 3 is constant => one channel pair per thread, row advances 128/iter.
// W'[b][c][kb] = sum walk[r]*ds_c*a^{-(r+1)}. Temp table fused (b==0).
// ---------------------------------------------------------------------------
__global__ __launch_bounds__(PTPB) void prep_kernel(const float* __restrict__ walk) {
    __shared__ float2 red[3][128];

    const int bx = blockIdx.x;
    const int b = bx >> 6, kb = bx & 63;
    const int tid = threadIdx.x;
    const int ph = tid % 3, q = tid / 3;   // channel-pair phase, row-in-group
    const int c0 = 2 * ph;                  // channels (c0, c0+1)

    // batch b walk = 65535 rows * 6 floats = 196605 float2 (8B aligned)
    const float2* wp2 = (const float2*)walk + (size_t)b * 196605 + (size_t)kb * 3072;

    float ainv = expf((float)(kb * POSB + q + 1) * LPc);   // a^{-(r+1)}
    const int rbase = kb * POSB + q;

    float ax = 0.0f, ay = 0.0f;
    #pragma unroll
    for (int i = 0; i < 8; ++i) {
        const int r = rbase + 128 * i;          // row within batch
        float2 v = (r < LL - 1) ? wp2[tid + PTPB * i] : make_float2(0.0f, 0.0f);
        ax += v.x * ainv;
        ay += v.y * ainv;
        ainv *= STEP128;
    }
    const float dsx = ((c0     < 3) ? 0.2f : 0.015f) * SQc;
    const float dsy = ((c0 + 1 < 3) ? 0.2f : 0.015f) * SQc;
    red[ph][q] = make_float2(ax * dsx, ay * dsy);

    // temp table: b==0 blocks cover positions [kb*1024, +1024)
    if (b == 0) {
        for (int t = kb * POSB + tid; t < (kb + 1) * POSB; t += PTPB) {
            float tt = (float)t * INV_LM1;
            g_temp[t] = 20.0f + 5.0f * __sinf(TWO_PI * tt) + 2.0f * tt;
        }
    }
    __syncthreads();

    // warps 0..2 reduce phase 0..2 (128 float2 each), fixed order
    const int w = tid >> 5, l = tid & 31;
    if (w < 3) {
        float2 s0 = red[w][l], s1 = red[w][l + 32];
        float2 s2 = red[w][l + 64], s3 = red[w][l + 96];
        float sx = (s0.x + s1.x) + (s2.x + s3.x);
        float sy = (s0.y + s1.y) + (s2.y + s3.y);
        #pragma unroll
        for (int d = 16; d >= 1; d >>= 1) {
            sx += __shfl_down_sync(0xffffffffu, sx, d);
            sy += __shfl_down_sync(0xffffffffu, sy, d);
        }
        if (l == 0) {
            g_W[(b * CC + 2 * w) * NCH + kb] = sx;
            g_W[(b * CC + 2 * w + 1) * NCH + kb] = sy;
        }
    }
}

// ---------------------------------------------------------------------------
// Carry: exclusive prefix over 64 blocks, one warp per (b,c) pair.
// ---------------------------------------------------------------------------
__global__ __launch_bounds__(1024) void carry_kernel() {
    const int w = threadIdx.x >> 5, l = threadIdx.x & 31;
    const int pair = blockIdx.x * 32 + w;       // 0..191 == (b*CC+c)
    const float* src = &g_W[pair * NCH];
    float* dst = &g_E[pair * NCH];

    float2 v = *(const float2*)(src + 2 * l);
    float s = v.x + v.y;
    float inc = s;
    #pragma unroll
    for (int d = 1; d < 32; d <<= 1) {
        float o = __shfl_up_sync(0xffffffffu, inc, d);
        if (l >= d) inc += o;
    }
    float excl = inc - s;
    float2 e; e.x = excl; e.y = excl + v.x;
    *(float2*)(dst + 2 * l) = e;
}

// ---------------------------------------------------------------------------
// Apply (proven round-4 core). Carry now includes row tstart-1's term, so
// local tid 0 zeroes w0 in every chunk.
// ---------------------------------------------------------------------------
__global__ __launch_bounds__(TPB, 2) void apply_kernel(
    const float* __restrict__ imu,
    const float* __restrict__ eps0,
    const float* __restrict__ walk,
    const float* __restrict__ meas,
    float* __restrict__ out)
{
    __shared__ float wsum[16][CC];
    __shared__ float wexc[16][CC];

    const int bx = blockIdx.x;
    const int b = bx >> 6, k = bx & (NCH - 1);
    const int tid = threadIdx.x;
    const int w = tid >> 5, l = tid & 31;
    const int tstart = k * POSB;
    const int p0 = tstart + tid * 2;

    float wv[12];
    load_walk12(walk, b, p0, wv);

    const float ainv0 = expf((float)p0 * LPc);
    const float ainv1 = ainv0 * (1.0f + LPc);
    const float apos0 = expf(-(float)p0 * LPc);
    const float apos1 = apos0 * (1.0f - LPc);

    float w0[CC], w1[CC], t6[CC];
    #pragma unroll
    for (int c = 0; c < CC; ++c) {
        float ds = ch_std0(c) * SQc;
        w0[c] = wv[c] * ds * ainv0;
        w1[c] = wv[6 + c] * ds * ainv1;
    }
    if (tid == 0) {
        #pragma unroll
        for (int c = 0; c < CC; ++c) w0[c] = 0.0f;   // row tstart-1 term is in carry
    }
    #pragma unroll
    for (int c = 0; c < CC; ++c) t6[c] = w0[c] + w1[c];

    float incl[CC];
    #pragma unroll
    for (int c = 0; c < CC; ++c) incl[c] = t6[c];
    #pragma unroll
    for (int d = 1; d < 32; d <<= 1)
        #pragma unroll
        for (int c = 0; c < CC; ++c) {
            float o = __shfl_up_sync(0xffffffffu, incl[c], d);
            if (l >= d) incl[c] += o;
        }
    if (l == 31)
        #pragma unroll
        for (int c = 0; c < CC; ++c) wsum[w][c] = incl[c];
    __syncthreads();

    if (w == 0 && l < 16) {
        float v[CC], inc2[CC];
        #pragma unroll
        for (int c = 0; c < CC; ++c) { v[c] = wsum[l][c]; inc2[c] = v[c]; }
        #pragma unroll
        for (int d = 1; d < 16; d <<= 1)
            #pragma unroll
            for (int c = 0; c < CC; ++c) {
                float o = __shfl_up_sync(0x0000ffffu, inc2[c], d);
                if (l >= d) inc2[c] += o;
            }
        #pragma unroll
        for (int c = 0; c < CC; ++c) wexc[l][c] = inc2[c] - v[c];
    }
    __syncthreads();

    float bias0[CC], bias1[CC];
    #pragma unroll
    for (int c = 0; c < CC; ++c) {
        float carry = eps0[b * CC + c] * ch_std0(c) + g_E[(b * CC + c) * NCH + k];
        float base = carry + wexc[w][c] + (incl[c] - t6[c]);
        bias0[c] = (base + w0[c]) * apos0;
        bias1[c] = (base + t6[c]) * apos1;
    }

    const size_t gb = ((size_t)b * LL + tstart) * CC + (size_t)tid * 12;
    const float tm0 = g_temp[p0], tm1 = g_temp[p0 + 1];

    float bias[12], tadd[12], ns[12];
    #pragma unroll
    for (int c = 0; c < CC; ++c) {
        bias[c] = bias0[c];           bias[6 + c] = bias1[c];
        tadd[c] = tm0 * ch_tcoef(c);  tadd[6 + c] = tm1 * ch_tcoef(c);
        ns[c] = ch_noise(c);          ns[6 + c] = ch_noise(c);
    }
    #pragma unroll
    for (int q = 0; q < 3; ++q) {
        float4 vi = *(const float4*)(imu + gb + q * 4);
        float4 vm = *(const float4*)(meas + gb + q * 4);
        float4 o4;
        o4.x = vi.x + bias[q * 4 + 0] + vm.x * ns[q * 4 + 0] + tadd[q * 4 + 0];
        o4.y = vi.y + bias[q * 4 + 1] + vm.y * ns[q * 4 + 1] + tadd[q * 4 + 1];
        o4.z = vi.z + bias[q * 4 + 2] + vm.z * ns[q * 4 + 2] + tadd[q * 4 + 2];
        o4.w = vi.w + bias[q * 4 + 3] + vm.w * ns[q * 4 + 3] + tadd[q * 4 + 3];
        *(float4*)(out + gb + q * 4) = o4;
    }
}

// ---------------------------------------------------------------------------
extern "C" void kernel_launch(void* const* d_in, const int* in_sizes, int n_in,
                              void* d_out, int out_size) {
    const float* imu  = (const float*)d_in[0];   // [32, 4096, 16, 6]
    const float* eps0 = (const float*)d_in[1];   // [32, 6]
    const float* walk = (const float*)d_in[2];   // [32, 65535, 6]
    const float* meas = (const float*)d_in[3];   // [32, 65536, 6]
    float* out = (float*)d_out;

    prep_kernel<<<GRID_P, PTPB>>>(walk);
    carry_kernel<<<CC, 1024>>>();
    apply_kernel<<<GRID_A, TPB>>>(imu, eps0, walk, meas, out);
}